// round 1
// baseline (speedup 1.0000x reference)
#include <cuda_runtime.h>
#include <cuda_bf16.h>
#include <cstdint>
#include <cstddef>

// Problem constants (fixed shapes)
//   B=256, N=50 -> PAIRS=12800; K=12 adj items; D=128
#define PAIRS      12800
#define D_         128
#define KADJ       12
// GEMM1: per 2-pair chunk: M=128 (d, 8 m16-tiles), N=24 (rows, 3 n8-tiles), K=144 (c padded, 9 k16-steps)
#define G1_KS      9
#define G1_MT      8
#define G1_NT      3
// GEMM2: M=pairs, N=128 (16 n8-tiles), K=256 (16 k16-steps)
#define G2_KS      16
#define G2_NT      16

// ---------------- device scratch (no allocation allowed) ----------------
__device__ __align__(16) uint32_t g_w1Ah[G1_KS * G1_MT * 32 * 4];   // [ks][mt][lane][r]
__device__ __align__(16) uint32_t g_w1Al[G1_KS * G1_MT * 32 * 4];
__device__ __align__(16) uint32_t g_w3Bh[G2_KS * G2_NT * 32 * 2];   // [ks][nt][lane][r]
__device__ __align__(16) uint32_t g_w3Bl[G2_KS * G2_NT * 32 * 2];
__device__ float g_att[(size_t)PAIRS * D_];

// ---------------- helpers ----------------
__device__ __forceinline__ uint32_t pack_split(float v0, float v1, uint32_t& lo_out) {
    // split each fp32 into hi(bf16) + lo(bf16 of residual); pack [v0|v1] with v0 in low half
    __nv_bfloat16 h0 = __float2bfloat16_rn(v0);
    __nv_bfloat16 h1 = __float2bfloat16_rn(v1);
    float r0 = v0 - __bfloat162float(h0);
    float r1 = v1 - __bfloat162float(h1);
    __nv_bfloat16 l0 = __float2bfloat16_rn(r0);
    __nv_bfloat16 l1 = __float2bfloat16_rn(r1);
    __nv_bfloat162 hh = __halves2bfloat162(h0, h1);
    __nv_bfloat162 ll = __halves2bfloat162(l0, l1);
    uint32_t hi;
    memcpy(&hi, &hh, 4);
    memcpy(&lo_out, &ll, 4);
    return hi;
}

__device__ __forceinline__ void mma16816(float& c0, float& c1, float& c2, float& c3,
                                         uint32_t a0, uint32_t a1, uint32_t a2, uint32_t a3,
                                         uint32_t b0, uint32_t b1) {
    asm volatile(
        "mma.sync.aligned.m16n8k16.row.col.f32.bf16.bf16.f32 "
        "{%0,%1,%2,%3}, {%4,%5,%6,%7}, {%8,%9}, {%0,%1,%2,%3};\n"
        : "+f"(c0), "+f"(c1), "+f"(c2), "+f"(c3)
        : "r"(a0), "r"(a1), "r"(a2), "r"(a3), "r"(b0), "r"(b1));
}

__device__ __forceinline__ float lky(float v) { return fmaxf(v, 0.2f * v); }

// ---------------- K0: pre-pack w1 / w3 into split-bf16 fragment layout ----------------
// m16n8k16 fragment maps (lane = tid%32):
//   A regs r=0..3: m = lane/4 + (r&1)*8 ; k = (lane%4)*2 + (r>>1)*8 + {0,1}
//   B regs r=0..1: k = (lane%4)*2 + r*8 + {0,1} ; n = lane/4
//   C regs: c0:(m=lane/4, n=(lane%4)*2) c1:(n+1) c2:(m+8,n) c3:(m+8,n+1)
__global__ void prep_frags(const float* __restrict__ w1, const float* __restrict__ w3) {
    int idx = blockIdx.x * blockDim.x + threadIdx.x;
    if (idx < G1_KS * G1_MT * 32 * 4) {
        // GEMM1 A operand = w1^T : A[m=d][k=c] = w1[c][d], c padded to 144 with zeros
        int r = idx & 3, lane = (idx >> 2) & 31, mt = (idx >> 7) & 7, ks = idx >> 10;
        int m  = mt * 16 + (lane >> 2) + (r & 1) * 8;          // d in [0,128)
        int k0 = ks * 16 + (lane & 3) * 2 + (r >> 1) * 8;      // c
        float v0 = (k0     < 129) ? w1[k0 * 128 + m]       : 0.f;
        float v1 = (k0 + 1 < 129) ? w1[(k0 + 1) * 128 + m] : 0.f;
        uint32_t lo, hi = pack_split(v0, v1, lo);
        g_w1Ah[idx] = hi; g_w1Al[idx] = lo;
    } else if (idx < G1_KS * G1_MT * 32 * 4 + G2_KS * G2_NT * 32 * 2) {
        // GEMM2 B operand = w3 : B[k=c][n=d] = w3[c][d]
        int j = idx - G1_KS * G1_MT * 32 * 4;
        int r = j & 1, lane = (j >> 1) & 31, nt = (j >> 6) & 15, ks = j >> 10;
        int n  = nt * 8 + (lane >> 2);                          // d
        int k0 = ks * 16 + (lane & 3) * 2 + r * 8;              // c in [0,256)
        float v0 = w3[k0 * 128 + n];
        float v1 = w3[(k0 + 1) * 128 + n];
        uint32_t lo, hi = pack_split(v0, v1, lo);
        g_w3Bh[j] = hi; g_w3Bl[j] = lo;
    }
}

// ---------------- Kernel 1: attention part -> att ----------------
struct Smem1 {
    uint32_t w1Ah[G1_KS * G1_MT * 32 * 4];  // 36864 B
    uint32_t w1Al[G1_KS * G1_MT * 32 * 4];  // 36864 B
    uint32_t preBh[G1_KS * G1_NT * 32 * 2]; // 6912 B
    uint32_t preBl[G1_KS * G1_NT * 32 * 2]; // 6912 B
    float adj[2][KADJ][D_];                 // 12288 B (raw, reused for att)
    float ave[2][D_];                       // 1024 B
    float w2s[D_];                          // 512 B
    float wgt[2][KADJ];                     // 96 B
    float lpart[8][24];                     // 768 B : per-warp logit partials (deterministic reduce)
    float alpha[24];                        // 96 B
};

__device__ __forceinline__ float pre_val(const Smem1& s, int p, int kk, int c) {
    if (c < 128)  return s.ave[p][c] * s.adj[p][kk][c];
    if (c == 128) return s.wgt[p][kk];
    return 0.f;
}

__global__ void __launch_bounds__(256, 2) kernel1(
    const float* __restrict__ ave_g, const float* __restrict__ adj_g,
    const float* __restrict__ wgt_g, const float* __restrict__ w2_g) {
    extern __shared__ __align__(16) unsigned char smem_raw[];
    Smem1& s = *reinterpret_cast<Smem1*>(smem_raw);
    const int tid = threadIdx.x, warp = tid >> 5, lane = tid & 31;

    // stage w1 fragments (shared by 16 pairs -> amortized L2 traffic)
    for (int i = tid; i < G1_KS * G1_MT * 32 * 4; i += 256) {
        s.w1Ah[i] = g_w1Ah[i];
        s.w1Al[i] = g_w1Al[i];
    }
    if (tid < 128) s.w2s[tid] = w2_g[tid];

    const int pairBase = blockIdx.x * 16;
    for (int chunk = 0; chunk < 8; chunk++) {
        const int p0 = pairBase + chunk * 2;
        __syncthreads();  // previous chunk fully consumed s.adj / s.alpha

        // load raw tiles for 2 pairs (coalesced)
        float* adj_flat = &s.adj[0][0][0];
        for (int i = tid; i < 2 * KADJ * D_; i += 256)
            adj_flat[i] = adj_g[(size_t)p0 * (KADJ * D_) + i];
        ((float*)s.ave)[tid] = ave_g[(size_t)p0 * D_ + tid];
        if (tid < 24) ((float*)s.wgt)[tid] = wgt_g[p0 * KADJ + tid];
        __syncthreads();

        // build pre = [ave*adj | wgt | 0pad] as split-bf16 B fragments
        for (int i = tid; i < G1_KS * G1_NT * 32 * 2; i += 256) {
            int r = i & 1, ln = (i >> 1) & 31;
            int g6 = i >> 6; int nt = g6 % 3, ks = g6 / 3;
            int row = nt * 8 + (ln >> 2);            // 0..23
            int p = row / KADJ, kk = row - p * KADJ;
            int c0 = ks * 16 + (ln & 3) * 2 + r * 8;
            float v0 = pre_val(s, p, kk, c0);
            float v1 = pre_val(s, p, kk, c0 + 1);
            uint32_t lo, hi = pack_split(v0, v1, lo);
            s.preBh[i] = hi; s.preBl[i] = lo;
        }
        __syncthreads();

        // GEMM1: acc[nt] = alpha1[d-tile=warp][row-tile=nt]  (3-product split-bf16)
        float acc[G1_NT][4];
        #pragma unroll
        for (int nt = 0; nt < G1_NT; nt++)
            #pragma unroll
            for (int j = 0; j < 4; j++) acc[nt][j] = 0.f;

        #pragma unroll
        for (int ks = 0; ks < G1_KS; ks++) {
            const uint4 Ah = *(const uint4*)&s.w1Ah[((ks * G1_MT + warp) * 32 + lane) * 4];
            const uint4 Al = *(const uint4*)&s.w1Al[((ks * G1_MT + warp) * 32 + lane) * 4];
            #pragma unroll
            for (int nt = 0; nt < G1_NT; nt++) {
                const uint2 Bh = *(const uint2*)&s.preBh[((ks * G1_NT + nt) * 32 + lane) * 2];
                const uint2 Bl = *(const uint2*)&s.preBl[((ks * G1_NT + nt) * 32 + lane) * 2];
                mma16816(acc[nt][0], acc[nt][1], acc[nt][2], acc[nt][3],
                         Ah.x, Ah.y, Ah.z, Ah.w, Bh.x, Bh.y);
                mma16816(acc[nt][0], acc[nt][1], acc[nt][2], acc[nt][3],
                         Ah.x, Ah.y, Ah.z, Ah.w, Bl.x, Bl.y);
                mma16816(acc[nt][0], acc[nt][1], acc[nt][2], acc[nt][3],
                         Al.x, Al.y, Al.z, Al.w, Bh.x, Bh.y);
            }
        }

        // epilogue: logits[row] = sum_d leaky(alpha1[d][row]) * w2[d]
        const float w2lo = s.w2s[warp * 16 + (lane >> 2)];
        const float w2hi = s.w2s[warp * 16 + (lane >> 2) + 8];
        float part[6];
        #pragma unroll
        for (int nt = 0; nt < G1_NT; nt++) {
            part[nt * 2 + 0] = lky(acc[nt][0]) * w2lo + lky(acc[nt][2]) * w2hi;
            part[nt * 2 + 1] = lky(acc[nt][1]) * w2lo + lky(acc[nt][3]) * w2hi;
        }
        #pragma unroll
        for (int j = 0; j < 6; j++) {
            part[j] += __shfl_xor_sync(0xffffffffu, part[j], 4);
            part[j] += __shfl_xor_sync(0xffffffffu, part[j], 8);
            part[j] += __shfl_xor_sync(0xffffffffu, part[j], 16);
        }
        if (lane < 4) {  // lanes 0..3 hold full d-sums of this warp's tile
            #pragma unroll
            for (int nt = 0; nt < G1_NT; nt++) {
                s.lpart[warp][nt * 8 + lane * 2 + 0] = part[nt * 2 + 0];
                s.lpart[warp][nt * 8 + lane * 2 + 1] = part[nt * 2 + 1];
            }
        }
        __syncthreads();

        // softmax over K=12 (warp 0 -> pair 0, warp 1 -> pair 1) : deterministic fixed-order sum
        if (warp < 2) {
            float lg = -1e30f;
            if (lane < KADJ) {
                lg = 0.f;
                #pragma unroll
                for (int w = 0; w < 8; w++) lg += s.lpart[w][warp * KADJ + lane];
            }
            float mx = lg;
            #pragma unroll
            for (int m2 = 16; m2 > 0; m2 >>= 1) mx = fmaxf(mx, __shfl_xor_sync(0xffffffffu, mx, m2));
            float e = (lane < KADJ) ? expf(lg - mx) : 0.f;
            float sm = e;
            #pragma unroll
            for (int m2 = 16; m2 > 0; m2 >>= 1) sm += __shfl_xor_sync(0xffffffffu, sm, m2);
            if (lane < KADJ) s.alpha[warp * KADJ + lane] = e / sm;
        }
        __syncthreads();

        // att[p][d] = sum_k alpha[k] * adj[p][k][d]  (fp32, conflict-free)
        {
            const int p = tid >> 7, d = tid & 127;
            float a = 0.f;
            #pragma unroll
            for (int k = 0; k < KADJ; k++) a += s.alpha[p * KADJ + k] * s.adj[p][k][d];
            g_att[(size_t)(p0 + p) * D_ + d] = a;
        }
    }
}

// ---------------- Kernel 2: out = relu([itm|att] @ w3) ----------------
__global__ void __launch_bounds__(256) kernel2(const float* __restrict__ itm,
                                               float* __restrict__ out) {
    __shared__ __align__(16) uint32_t Ah_s[2 * G2_KS * 32 * 4];  // [mt][ks][lane][r]
    __shared__ __align__(16) uint32_t Al_s[2 * G2_KS * 32 * 4];
    const int tid = threadIdx.x, warp = tid >> 5, lane = tid & 31;
    const int pairBase = blockIdx.x * 32;

    // build A fragments for 32 rows of g = [itm | att]
    for (int i = tid; i < 2 * G2_KS * 32 * 4; i += 256) {
        int r = i & 3, ln = (i >> 2) & 31, ks = (i >> 7) & 15, mt = i >> 11;
        int row = pairBase + mt * 16 + (ln >> 2) + (r & 1) * 8;
        int c0 = ks * 16 + (ln & 3) * 2 + (r >> 1) * 8;
        float v0 = (c0 < 128) ? itm[(size_t)row * D_ + c0]
                              : g_att[(size_t)row * D_ + (c0 - 128)];
        int c1 = c0 + 1;
        float v1 = (c1 < 128) ? itm[(size_t)row * D_ + c1]
                              : g_att[(size_t)row * D_ + (c1 - 128)];
        uint32_t lo, hi = pack_split(v0, v1, lo);
        Ah_s[i] = hi; Al_s[i] = lo;
    }
    __syncthreads();

    const int mt = warp >> 2;       // 0..1 : which 16 pairs
    const int ng = warp & 3;        // 0..3 : which 4 n8-tiles
    float acc[4][4];
    #pragma unroll
    for (int j = 0; j < 4; j++)
        #pragma unroll
        for (int q = 0; q < 4; q++) acc[j][q] = 0.f;

    #pragma unroll
    for (int ks = 0; ks < G2_KS; ks++) {
        const uint4 Ah = *(const uint4*)&Ah_s[((mt * G2_KS + ks) * 32 + lane) * 4];
        const uint4 Al = *(const uint4*)&Al_s[((mt * G2_KS + ks) * 32 + lane) * 4];
        #pragma unroll
        for (int j = 0; j < 4; j++) {
            int nt = ng * 4 + j;
            const uint2 Bh = *(const uint2*)&g_w3Bh[((ks * G2_NT + nt) * 32 + lane) * 2];
            const uint2 Bl = *(const uint2*)&g_w3Bl[((ks * G2_NT + nt) * 32 + lane) * 2];
            mma16816(acc[j][0], acc[j][1], acc[j][2], acc[j][3],
                     Ah.x, Ah.y, Ah.z, Ah.w, Bh.x, Bh.y);
            mma16816(acc[j][0], acc[j][1], acc[j][2], acc[j][3],
                     Ah.x, Ah.y, Ah.z, Ah.w, Bl.x, Bl.y);
            mma16816(acc[j][0], acc[j][1], acc[j][2], acc[j][3],
                     Al.x, Al.y, Al.z, Al.w, Bh.x, Bh.y);
        }
    }

    // relu + store
    #pragma unroll
    for (int j = 0; j < 4; j++) {
        int nt = ng * 4 + j;
        int d = nt * 8 + (lane & 3) * 2;
        int row0 = pairBase + mt * 16 + (lane >> 2);
        float2 v0 = make_float2(fmaxf(acc[j][0], 0.f), fmaxf(acc[j][1], 0.f));
        float2 v1 = make_float2(fmaxf(acc[j][2], 0.f), fmaxf(acc[j][3], 0.f));
        *(float2*)&out[(size_t)row0 * D_ + d]       = v0;
        *(float2*)&out[(size_t)(row0 + 8) * D_ + d] = v1;
    }
}

// ---------------- launch ----------------
extern "C" void kernel_launch(void* const* d_in, const int* in_sizes, int n_in,
                              void* d_out, int out_size) {
    const float *itm = nullptr, *ave = nullptr, *adj = nullptr, *wgt = nullptr;
    const float *w1 = nullptr, *w2 = nullptr, *w3 = nullptr;
    for (int i = 0; i < n_in; i++) {
        const float* p = (const float*)d_in[i];
        switch (in_sizes[i]) {
            case 1638400:  if (!itm) itm = p; else ave = p; break;  // itm first, then ave
            case 19660800: adj = p; break;
            case 153600:   wgt = p; break;
            case 16512:    w1 = p; break;
            case 128:      w2 = p; break;
            case 32768:    w3 = p; break;
            default: break;  // batch_size scalar etc.
        }
    }

    cudaFuncSetAttribute(kernel1, cudaFuncAttributeMaxDynamicSharedMemorySize,
                         (int)sizeof(Smem1));

    prep_frags<<<100, 256>>>(w1, w3);
    kernel1<<<PAIRS / 16, 256, sizeof(Smem1)>>>(ave, adj, wgt, w2);
    kernel2<<<PAIRS / 32, 256>>>(itm, (float*)d_out);
}

// round 6
// speedup vs baseline: 1.2659x; 1.2659x over previous
#include <cuda_runtime.h>
#include <cuda_bf16.h>
#include <cstdint>
#include <cstddef>

// Shapes: B=256, N=50 -> PAIRS=12800; KADJ=12; D=128
#define PAIRS   12800
#define D_      128
#define KADJ    12
#define PPT     10            // pairs per tile (120 rows + 8 pad = 128)
#define TILES1  (PAIRS / PPT) // 1280
#define GRID1   148           // persistent CTAs

// ------------------------------------------------------------------ scratch
// B-fragment images, fragment-major [ks][nt][lane][r], m16n8k16 layout
__device__ __align__(16) uint32_t g_w1Bh[8 * 16 * 32 * 2];    // w1 (K=128, N=128)
__device__ __align__(16) uint32_t g_w1Bl[8 * 16 * 32 * 2];
__device__ __align__(16) uint32_t g_w3Bh[16 * 16 * 32 * 2];   // w3 (K=256, N=128)
__device__ __align__(16) uint32_t g_w3Bl[16 * 16 * 32 * 2];
__device__ float g_att[(size_t)PAIRS * D_];

// ------------------------------------------------------------------ helpers
__device__ __forceinline__ uint32_t pack_split(float v0, float v1, uint32_t& lo) {
    __nv_bfloat162 hh = __floats2bfloat162_rn(v0, v1);
    float r0 = v0 - __low2float(hh);
    float r1 = v1 - __high2float(hh);
    __nv_bfloat162 ll = __floats2bfloat162_rn(r0, r1);
    uint32_t hi;
    memcpy(&hi, &hh, 4); memcpy(&lo, &ll, 4);
    return hi;
}

__device__ __forceinline__ void mma16816(float* c, uint4 a, uint2 b) {
    asm volatile(
        "mma.sync.aligned.m16n8k16.row.col.f32.bf16.bf16.f32 "
        "{%0,%1,%2,%3}, {%4,%5,%6,%7}, {%8,%9}, {%0,%1,%2,%3};\n"
        : "+f"(c[0]), "+f"(c[1]), "+f"(c[2]), "+f"(c[3])
        : "r"(a.x), "r"(a.y), "r"(a.z), "r"(a.w), "r"(b.x), "r"(b.y));
}

// -------------------------------------------------------- prep: B fragments
// B-frag element map: n = nt*8 + lane/4 ; k = ks*16 + (lane%4)*2 + r*8 + {0,1}
__global__ void prep_frags(const float* __restrict__ w1, const float* __restrict__ w3) {
    int idx = blockIdx.x * blockDim.x + threadIdx.x;
    if (idx < 8 * 16 * 32 * 2) {
        int r = idx & 1, lane = (idx >> 1) & 31, nt = (idx >> 6) & 15, ks = idx >> 10;
        int n  = nt * 8 + (lane >> 2);
        int k0 = ks * 16 + (lane & 3) * 2 + r * 8;        // < 128 always
        uint32_t lo, hi = pack_split(w1[k0 * 128 + n], w1[(k0 + 1) * 128 + n], lo);
        g_w1Bh[idx] = hi; g_w1Bl[idx] = lo;
    } else {
        int j = idx - 8 * 16 * 32 * 2;                    // w3: 16384 entries
        int r = j & 1, lane = (j >> 1) & 31, nt = (j >> 6) & 15, ks = j >> 10;
        int n  = nt * 8 + (lane >> 2);
        int k0 = ks * 16 + (lane & 3) * 2 + r * 8;        // < 256
        uint32_t lo, hi = pack_split(w3[k0 * 128 + n], w3[(k0 + 1) * 128 + n], lo);
        g_w3Bh[j] = hi; g_w3Bl[j] = lo;
    }
}

// -------------------------------------------------------- kernel1 (attention)
// smem byte offsets
#define K1_AH   0         // 32768 : A frags hi [ks8][mt8][lane][4]
#define K1_AL   32768     // 32768
#define K1_BH   65536     // 32768 : w1 B frags
#define K1_BL   98304     // 32768
#define K1_ADJ  131072    // 61440 : 10*12*128 f32
#define K1_AVE  192512    // 5120  : 10*128 f32
#define K1_WGT  197632    // 480   -> pad 512
#define K1_W1L  198144    // 512
#define K1_W2   198656    // 512
#define K1_LOG  199168    // 512
#define K1_ALP  199680    // 480
#define K1_SIZE 200192

__global__ void __launch_bounds__(256, 1) kernel1(
    const float* __restrict__ ave_g, const float* __restrict__ adj_g,
    const float* __restrict__ wgt_g, const float* __restrict__ w1_g,
    const float* __restrict__ w2_g) {
    extern __shared__ __align__(16) unsigned char sm[];
    const int tid = threadIdx.x, warp = tid >> 5, lane = tid & 31;

    uint32_t* sAH = (uint32_t*)(sm + K1_AH);
    uint32_t* sAL = (uint32_t*)(sm + K1_AL);
    uint32_t* sBH = (uint32_t*)(sm + K1_BH);
    uint32_t* sBL = (uint32_t*)(sm + K1_BL);
    float* s_adj = (float*)(sm + K1_ADJ);
    float* s_ave = (float*)(sm + K1_AVE);
    float* s_wgt = (float*)(sm + K1_WGT);
    float* s_w1l = (float*)(sm + K1_W1L);
    float* s_w2  = (float*)(sm + K1_W2);
    float* s_log = (float*)(sm + K1_LOG);
    float* s_alp = (float*)(sm + K1_ALP);

    // stage static operands once per CTA
    {
        const uint4* shx = (const uint4*)g_w1Bh;
        const uint4* slx = (const uint4*)g_w1Bl;
        uint4* dh = (uint4*)sBH; uint4* dl = (uint4*)sBL;
        for (int i = tid; i < 2048; i += 256) { dh[i] = shx[i]; dl[i] = slx[i]; }
        if (tid < 128) { s_w2[tid] = w2_g[tid]; s_w1l[tid] = w1_g[128 * 128 + tid]; }
    }

    // per-lane constants
    const int m_lo = warp * 16 + (lane >> 2), m_hi = m_lo + 8;
    const int p_lo = m_lo / 12, kk_lo = m_lo - p_lo * 12;
    const int p_hi = m_hi / 12, kk_hi = m_hi - p_hi * 12;
    const bool v_lo = m_lo < PPT * KADJ, v_hi = m_hi < PPT * KADJ;

    for (int tile = blockIdx.x; tile < TILES1; tile += GRID1) {
        const size_t pbase = (size_t)tile * PPT;
        __syncthreads();   // previous tile fully consumed s_adj / logits
        // ---- load raw tile ----
        {
            const float4* a4 = (const float4*)(adj_g + pbase * (KADJ * D_));
            float4* d4 = (float4*)s_adj;
            #pragma unroll 4
            for (int i = tid; i < PPT * KADJ * D_ / 4; i += 256) d4[i] = a4[i];
            const float4* v4 = (const float4*)(ave_g + pbase * D_);
            float4* e4 = (float4*)s_ave;
            for (int i = tid; i < PPT * D_ / 4; i += 256) e4[i] = v4[i];  // 320 entries, strided
            if (tid < PPT * KADJ) s_wgt[tid] = wgt_g[pbase * KADJ + tid];
        }
        __syncthreads();
        // ---- build A = pre fragments (split bf16), frag id f=[ks][mt][lane] ----
        for (int f = tid; f < 2048; f += 256) {
            const int ln = f & 31, mt = (f >> 5) & 7, ks = f >> 8;
            const int ma = mt * 16 + (ln >> 2), mb = ma + 8;
            const int k0 = ks * 16 + (ln & 3) * 2, k8 = k0 + 8;
            const int pa = ma / 12, ka = ma - pa * 12; const bool va = ma < 120;
            const int pb = mb / 12, kb = mb - pb * 12; const bool vb = mb < 120;
            uint4 H, L;
            float2 z = make_float2(0.f, 0.f);
            float2 aa0 = va ? *(const float2*)(s_ave + pa * D_ + k0) : z;
            float2 aa8 = va ? *(const float2*)(s_ave + pa * D_ + k8) : z;
            float2 ab0 = vb ? *(const float2*)(s_ave + pb * D_ + k0) : z;
            float2 ab8 = vb ? *(const float2*)(s_ave + pb * D_ + k8) : z;
            float2 da0 = va ? *(const float2*)(s_adj + (pa * KADJ + ka) * D_ + k0) : z;
            float2 da8 = va ? *(const float2*)(s_adj + (pa * KADJ + ka) * D_ + k8) : z;
            float2 db0 = vb ? *(const float2*)(s_adj + (pb * KADJ + kb) * D_ + k0) : z;
            float2 db8 = vb ? *(const float2*)(s_adj + (pb * KADJ + kb) * D_ + k8) : z;
            H.x = pack_split(aa0.x * da0.x, aa0.y * da0.y, L.x);
            H.y = pack_split(ab0.x * db0.x, ab0.y * db0.y, L.y);
            H.z = pack_split(aa8.x * da8.x, aa8.y * da8.y, L.z);
            H.w = pack_split(ab8.x * db8.x, ab8.y * db8.y, L.w);
            *(uint4*)&sAH[f * 4] = H;
            *(uint4*)&sAL[f * 4] = L;
        }
        __syncthreads();
        // ---- GEMM: 16 independent n-tiles per warp, 3-product split-bf16 ----
        float acc[16][4];
        #pragma unroll
        for (int nt = 0; nt < 16; nt++)
            #pragma unroll
            for (int q = 0; q < 4; q++) acc[nt][q] = 0.f;
        #pragma unroll
        for (int ks = 0; ks < 8; ks++) {
            const uint4 Ah = *(const uint4*)&sAH[((ks * 8 + warp) * 32 + lane) * 4];
            const uint4 Al = *(const uint4*)&sAL[((ks * 8 + warp) * 32 + lane) * 4];
            #pragma unroll
            for (int nt = 0; nt < 16; nt++) {
                const uint2 Bh = *(const uint2*)&sBH[((ks * 16 + nt) * 32 + lane) * 2];
                const uint2 Bl = *(const uint2*)&sBL[((ks * 16 + nt) * 32 + lane) * 2];
                mma16816(acc[nt], Ah, Bh);
                mma16816(acc[nt], Ah, Bl);
                mma16816(acc[nt], Al, Bh);
            }
        }
        // ---- epilogue: rank-1 wgt correction + leaky + w2 dot ----
        const float wv_lo = v_lo ? s_wgt[p_lo * KADJ + kk_lo] : 0.f;
        const float wv_hi = v_hi ? s_wgt[p_hi * KADJ + kk_hi] : 0.f;
        float part0 = 0.f, part1 = 0.f;
        #pragma unroll
        for (int nt = 0; nt < 16; nt++) {
            #pragma unroll
            for (int j = 0; j < 2; j++) {
                const int c = nt * 8 + (lane & 3) * 2 + j;
                const float w1lc = s_w1l[c], w2c = s_w2[c];
                float a = fmaf(wv_lo, w1lc, acc[nt][j]);
                part0 = fmaf(fmaxf(a, 0.2f * a), w2c, part0);
                float b = fmaf(wv_hi, w1lc, acc[nt][2 + j]);
                part1 = fmaf(fmaxf(b, 0.2f * b), w2c, part1);
            }
        }
        part0 += __shfl_xor_sync(0xffffffffu, part0, 1);
        part0 += __shfl_xor_sync(0xffffffffu, part0, 2);
        part1 += __shfl_xor_sync(0xffffffffu, part1, 1);
        part1 += __shfl_xor_sync(0xffffffffu, part1, 2);
        if ((lane & 3) == 0) { s_log[m_lo] = part0; s_log[m_hi] = part1; }
        __syncthreads();
        // ---- softmax per pair (serial, 10 threads, deterministic) ----
        if (tid < PPT) {
            const float* lg = s_log + tid * KADJ;
            float mx = lg[0];
            #pragma unroll
            for (int k = 1; k < KADJ; k++) mx = fmaxf(mx, lg[k]);
            float e[KADJ], ssum = 0.f;
            #pragma unroll
            for (int k = 0; k < KADJ; k++) { e[k] = __expf(lg[k] - mx); ssum += e[k]; }
            const float inv = 1.f / ssum;
            #pragma unroll
            for (int k = 0; k < KADJ; k++) s_alp[tid * KADJ + k] = e[k] * inv;
        }
        __syncthreads();
        // ---- att = sum_k alpha * adj (fp32 exact) ----
        #pragma unroll
        for (int i = tid; i < PPT * D_; i += 256) {
            const int p = i >> 7, d = i & 127;
            const float* adp = s_adj + p * (KADJ * D_) + d;
            float a = 0.f;
            #pragma unroll
            for (int k = 0; k < KADJ; k++) a = fmaf(s_alp[p * KADJ + k], adp[k * D_], a);
            g_att[(pbase + p) * D_ + d] = a;
        }
    }
}

// -------------------------------------------------------- kernel2 (w3 + relu)
#define K2_BH   0         // 65536 : w3 frags hi [ks16][nt16][lane][2]
#define K2_BL   65536     // 65536
#define K2_AH   131072    // 32768
#define K2_AL   163840    // 32768
#define K2_SIZE 196608

__global__ void __launch_bounds__(256, 1) kernel2(const float* __restrict__ itm,
                                                  float* __restrict__ out) {
    extern __shared__ __align__(16) unsigned char sm[];
    const int tid = threadIdx.x, warp = tid >> 5, lane = tid & 31;
    uint32_t* sBH = (uint32_t*)(sm + K2_BH);
    uint32_t* sBL = (uint32_t*)(sm + K2_BL);
    uint32_t* sAH = (uint32_t*)(sm + K2_AH);
    uint32_t* sAL = (uint32_t*)(sm + K2_AL);

    {
        const uint4* shx = (const uint4*)g_w3Bh;
        const uint4* slx = (const uint4*)g_w3Bl;
        uint4* dh = (uint4*)sBH; uint4* dl = (uint4*)sBL;
        for (int i = tid; i < 4096; i += 256) { dh[i] = shx[i]; dl[i] = slx[i]; }
    }

    const size_t rowbase = (size_t)blockIdx.x * 128;
    float acc[16][4];
    #pragma unroll
    for (int nt = 0; nt < 16; nt++)
        #pragma unroll
        for (int q = 0; q < 4; q++) acc[nt][q] = 0.f;

    #pragma unroll
    for (int half = 0; half < 2; half++) {
        const float* src = half ? (const float*)g_att : itm;
        __syncthreads();   // A buffer free (half 0: after B copy; half 1: after mma reads)
        for (int f = tid; f < 2048; f += 256) {
            const int ln = f & 31, mt = (f >> 5) & 7, ks = f >> 8;
            const size_t ra = rowbase + mt * 16 + (ln >> 2), rb = ra + 8;
            const int k0 = ks * 16 + (ln & 3) * 2, k8 = k0 + 8;
            float2 fa0 = *(const float2*)(src + ra * D_ + k0);
            float2 fb0 = *(const float2*)(src + rb * D_ + k0);
            float2 fa8 = *(const float2*)(src + ra * D_ + k8);
            float2 fb8 = *(const float2*)(src + rb * D_ + k8);
            uint4 H, L;
            H.x = pack_split(fa0.x, fa0.y, L.x);
            H.y = pack_split(fb0.x, fb0.y, L.y);
            H.z = pack_split(fa8.x, fa8.y, L.z);
            H.w = pack_split(fb8.x, fb8.y, L.w);
            *(uint4*)&sAH[f * 4] = H;
            *(uint4*)&sAL[f * 4] = L;
        }
        __syncthreads();
        #pragma unroll
        for (int ks = 0; ks < 8; ks++) {
            const int gks = half * 8 + ks;
            const uint4 Ah = *(const uint4*)&sAH[((ks * 8 + warp) * 32 + lane) * 4];
            const uint4 Al = *(const uint4*)&sAL[((ks * 8 + warp) * 32 + lane) * 4];
            #pragma unroll
            for (int nt = 0; nt < 16; nt++) {
                const uint2 Bh = *(const uint2*)&sBH[((gks * 16 + nt) * 32 + lane) * 2];
                const uint2 Bl = *(const uint2*)&sBL[((gks * 16 + nt) * 32 + lane) * 2];
                mma16816(acc[nt], Ah, Bh);
                mma16816(acc[nt], Ah, Bl);
                mma16816(acc[nt], Al, Bh);
            }
        }
    }
    // relu + store
    const size_t r_lo = rowbase + warp * 16 + (lane >> 2), r_hi = r_lo + 8;
    #pragma unroll
    for (int nt = 0; nt < 16; nt++) {
        const int c = nt * 8 + (lane & 3) * 2;
        *(float2*)(out + r_lo * D_ + c) =
            make_float2(fmaxf(acc[nt][0], 0.f), fmaxf(acc[nt][1], 0.f));
        *(float2*)(out + r_hi * D_ + c) =
            make_float2(fmaxf(acc[nt][2], 0.f), fmaxf(acc[nt][3], 0.f));
    }
}

// ------------------------------------------------------------------ launch
extern "C" void kernel_launch(void* const* d_in, const int* in_sizes, int n_in,
                              void* d_out, int out_size) {
    const float *itm = nullptr, *ave = nullptr, *adj = nullptr, *wgt = nullptr;
    const float *w1 = nullptr, *w2 = nullptr, *w3 = nullptr;
    for (int i = 0; i < n_in; i++) {
        const float* p = (const float*)d_in[i];
        switch (in_sizes[i]) {
            case 1638400:  if (!itm) itm = p; else ave = p; break;  // itm first, then ave
            case 19660800: adj = p; break;
            case 153600:   wgt = p; break;
            case 16512:    w1 = p; break;
            case 128:      w2 = p; break;
            case 32768:    w3 = p; break;
            default: break;
        }
    }
    cudaFuncSetAttribute(kernel1, cudaFuncAttributeMaxDynamicSharedMemorySize, K1_SIZE);
    cudaFuncSetAttribute(kernel2, cudaFuncAttributeMaxDynamicSharedMemorySize, K2_SIZE);

    prep_frags<<<96, 256>>>(w1, w3);
    kernel1<<<GRID1, 256, K1_SIZE>>>(ave, adj, wgt, w1, w2);
    kernel2<<<PAIRS / 128, 256, K2_SIZE>>>(itm, (float*)d_out);
}

// round 9
// speedup vs baseline: 1.4494x; 1.1450x over previous
#include <cuda_runtime.h>
#include <cuda_fp16.h>
#include <cstdint>
#include <cstddef>

// Shapes: B=256, N=50 -> PAIRS=12800; KADJ=12; D=128
#define PAIRS   12800
#define D_      128
#define KADJ    12
#define PPT     10            // pairs per tile (120 rows + 8 pad = 128)
#define TILES1  (PAIRS / PPT) // 1280
#define GRID1   148           // persistent CTAs
#define WSC     16.0f         // weight pre-scale (keeps fp16 residuals normal)
#define IWSC    0.0625f

// ------------------------------------------------------------------ scratch
// B fragments interleaved: uint4 = (Bh_r0, Bh_r1, Bl_r0, Bl_r1), index [ks][nt][lane]
__device__ __align__(16) uint4 g_w1B[8 * 16 * 32];     // w1 (K=128, N=128), 64KB
__device__ __align__(16) uint4 g_w3B[16 * 16 * 32];    // w3 (K=256, N=128), 128KB
__device__ float g_att[(size_t)PAIRS * D_];

// ------------------------------------------------------------------ helpers
__device__ __forceinline__ uint32_t h2(float v0, float v1) {
    __half2 h = __floats2half2_rn(v0, v1);
    uint32_t u; memcpy(&u, &h, 4); return u;
}
__device__ __forceinline__ void split16(float v, float& hi, float& lo) {
    hi = __half2float(__float2half_rn(v));
    lo = v - hi;
}
__device__ __forceinline__ void mma_fp16(float* c, uint4 a, uint32_t b0, uint32_t b1) {
    asm volatile(
        "mma.sync.aligned.m16n8k16.row.col.f32.f16.f16.f32 "
        "{%0,%1,%2,%3}, {%4,%5,%6,%7}, {%8,%9}, {%0,%1,%2,%3};\n"
        : "+f"(c[0]), "+f"(c[1]), "+f"(c[2]), "+f"(c[3])
        : "r"(a.x), "r"(a.y), "r"(a.z), "r"(a.w), "r"(b0), "r"(b1));
}

// -------------------------------------------------------- prep: B fragments
// B-frag element map (m16n8k16): n = nt*8 + lane/4 ; reg r: k = ks*16 + (lane%4)*2 + r*8 + {0,1}
__global__ void prep_frags(const float* __restrict__ w1, const float* __restrict__ w3) {
    int idx = blockIdx.x * blockDim.x + threadIdx.x;
    if (idx < 8 * 16 * 32) {
        int lane = idx & 31, nt = (idx >> 5) & 15, ks = idx >> 9;
        int n  = nt * 8 + (lane >> 2);
        int k0 = ks * 16 + (lane & 3) * 2;
        float v00 = w1[k0 * 128 + n] * WSC,       v01 = w1[(k0 + 1) * 128 + n] * WSC;
        float v10 = w1[(k0 + 8) * 128 + n] * WSC, v11 = w1[(k0 + 9) * 128 + n] * WSC;
        float h00, l00, h01, l01, h10, l10, h11, l11;
        split16(v00, h00, l00); split16(v01, h01, l01);
        split16(v10, h10, l10); split16(v11, h11, l11);
        uint4 B;
        B.x = h2(h00, h01); B.y = h2(h10, h11);
        B.z = h2(l00, l01); B.w = h2(l10, l11);
        g_w1B[idx] = B;
    } else if (idx < 8 * 16 * 32 + 16 * 16 * 32) {
        int j = idx - 8 * 16 * 32;
        int lane = j & 31, nt = (j >> 5) & 15, ks = j >> 9;
        int n  = nt * 8 + (lane >> 2);
        int k0 = ks * 16 + (lane & 3) * 2;
        float v00 = w3[k0 * 128 + n] * WSC,       v01 = w3[(k0 + 1) * 128 + n] * WSC;
        float v10 = w3[(k0 + 8) * 128 + n] * WSC, v11 = w3[(k0 + 9) * 128 + n] * WSC;
        float h00, l00, h01, l01, h10, l10, h11, l11;
        split16(v00, h00, l00); split16(v01, h01, l01);
        split16(v10, h10, l10); split16(v11, h11, l11);
        uint4 B;
        B.x = h2(h00, h01); B.y = h2(h10, h11);
        B.z = h2(l00, l01); B.w = h2(l10, l11);
        g_w3B[j] = B;
    }
}

// -------------------------------------------------------- kernel1 (attention)
// smem byte offsets
#define K1_A    0         // 32768 : A frags fp16 [ks8][mt8][lane][uint4]
#define K1_B    32768     // 65536 : w1 B frags interleaved uint4
#define K1_ADJ  98304     // 61440 : 10*12*128 f32
#define K1_AVE  159744    // 5120  : 10*128 f32
#define K1_WGT  164864    // 512
#define K1_W1L  165376    // 512
#define K1_W2   165888    // 512
#define K1_LOG  166400    // 512
#define K1_ALP  166912    // 512
#define K1_SIZE 167424

__global__ void __launch_bounds__(256, 1) kernel1(
    const float* __restrict__ ave_g, const float* __restrict__ adj_g,
    const float* __restrict__ wgt_g, const float* __restrict__ w1_g,
    const float* __restrict__ w2_g) {
    extern __shared__ __align__(16) unsigned char sm[];
    const int tid = threadIdx.x, warp = tid >> 5, lane = tid & 31;

    uint4* sA4 = (uint4*)(sm + K1_A);
    uint4* sB4 = (uint4*)(sm + K1_B);
    float* s_adj = (float*)(sm + K1_ADJ);
    float* s_ave = (float*)(sm + K1_AVE);
    float* s_wgt = (float*)(sm + K1_WGT);
    float* s_w1l = (float*)(sm + K1_W1L);
    float* s_w2  = (float*)(sm + K1_W2);
    float* s_log = (float*)(sm + K1_LOG);
    float* s_alp = (float*)(sm + K1_ALP);

    // stage static operands once per CTA
    for (int i = tid; i < 8 * 16 * 32; i += 256) sB4[i] = g_w1B[i];
    if (tid < 128) { s_w2[tid] = w2_g[tid]; s_w1l[tid] = w1_g[128 * 128 + tid]; }

    // per-lane constants (C-frag row map)
    const int m_lo = warp * 16 + (lane >> 2), m_hi = m_lo + 8;
    const int p_lo = m_lo / 12, kk_lo = m_lo - p_lo * 12;
    const int p_hi = m_hi / 12, kk_hi = m_hi - p_hi * 12;
    const bool v_lo = m_lo < PPT * KADJ, v_hi = m_hi < PPT * KADJ;

    for (int tile = blockIdx.x; tile < TILES1; tile += GRID1) {
        const size_t pbase = (size_t)tile * PPT;
        __syncthreads();   // previous tile fully consumed s_adj / logits
        // ---- load raw tile ----
        {
            const float4* a4 = (const float4*)(adj_g + pbase * (KADJ * D_));
            float4* d4 = (float4*)s_adj;
            #pragma unroll 4
            for (int i = tid; i < PPT * KADJ * D_ / 4; i += 256) d4[i] = a4[i];
            const float4* v4 = (const float4*)(ave_g + pbase * D_);
            float4* e4 = (float4*)s_ave;
            for (int i = tid; i < PPT * D_ / 4; i += 256) e4[i] = v4[i];   // 320, strided
            if (tid < PPT * KADJ) s_wgt[tid] = wgt_g[pbase * KADJ + tid];
        }
        __syncthreads();
        // ---- build A = pre fragments (single fp16), frag f=[ks][mt][lane] ----
        for (int f = tid; f < 2048; f += 256) {
            const int ln = f & 31, mt = (f >> 5) & 7, ks = f >> 8;
            const int ma = mt * 16 + (ln >> 2), mb = ma + 8;
            const int k0 = ks * 16 + (ln & 3) * 2, k8 = k0 + 8;
            const int pa = ma / 12, ka = ma - pa * 12; const bool va = ma < 120;
            const int pb = mb / 12, kb = mb - pb * 12; const bool vb = mb < 120;
            float2 z = make_float2(0.f, 0.f);
            float2 aa0 = va ? *(const float2*)(s_ave + pa * D_ + k0) : z;
            float2 aa8 = va ? *(const float2*)(s_ave + pa * D_ + k8) : z;
            float2 ab0 = vb ? *(const float2*)(s_ave + pb * D_ + k0) : z;
            float2 ab8 = vb ? *(const float2*)(s_ave + pb * D_ + k8) : z;
            float2 da0 = va ? *(const float2*)(s_adj + (pa * KADJ + ka) * D_ + k0) : z;
            float2 da8 = va ? *(const float2*)(s_adj + (pa * KADJ + ka) * D_ + k8) : z;
            float2 db0 = vb ? *(const float2*)(s_adj + (pb * KADJ + kb) * D_ + k0) : z;
            float2 db8 = vb ? *(const float2*)(s_adj + (pb * KADJ + kb) * D_ + k8) : z;
            uint4 H;
            H.x = h2(aa0.x * da0.x, aa0.y * da0.y);
            H.y = h2(ab0.x * db0.x, ab0.y * db0.y);
            H.z = h2(aa8.x * da8.x, aa8.y * da8.y);
            H.w = h2(ab8.x * db8.x, ab8.y * db8.y);
            sA4[f] = H;
        }
        __syncthreads();
        // ---- GEMM: 16 independent n-tiles per warp, 2-product split-fp16 ----
        float acc[16][4];
        #pragma unroll
        for (int nt = 0; nt < 16; nt++)
            #pragma unroll
            for (int q = 0; q < 4; q++) acc[nt][q] = 0.f;
        #pragma unroll
        for (int ks = 0; ks < 8; ks++) {
            const uint4 A = sA4[(ks * 8 + warp) * 32 + lane];
            #pragma unroll
            for (int nt = 0; nt < 16; nt++) {
                const uint4 B = sB4[(ks * 16 + nt) * 32 + lane];
                mma_fp16(acc[nt], A, B.x, B.y);   // A * Bh
                mma_fp16(acc[nt], A, B.z, B.w);   // A * Bl
            }
        }
        // ---- epilogue: unscale + rank-1 wgt correction + leaky + w2 dot ----
        const float wv_lo = v_lo ? s_wgt[p_lo * KADJ + kk_lo] : 0.f;
        const float wv_hi = v_hi ? s_wgt[p_hi * KADJ + kk_hi] : 0.f;
        float part0 = 0.f, part1 = 0.f;
        #pragma unroll
        for (int nt = 0; nt < 16; nt++) {
            #pragma unroll
            for (int j = 0; j < 2; j++) {
                const int c = nt * 8 + (lane & 3) * 2 + j;
                const float w1lc = s_w1l[c], w2c = s_w2[c];
                float a = fmaf(wv_lo, w1lc, acc[nt][j] * IWSC);
                part0 = fmaf(fmaxf(a, 0.2f * a), w2c, part0);
                float b = fmaf(wv_hi, w1lc, acc[nt][2 + j] * IWSC);
                part1 = fmaf(fmaxf(b, 0.2f * b), w2c, part1);
            }
        }
        part0 += __shfl_xor_sync(0xffffffffu, part0, 1);
        part0 += __shfl_xor_sync(0xffffffffu, part0, 2);
        part1 += __shfl_xor_sync(0xffffffffu, part1, 1);
        part1 += __shfl_xor_sync(0xffffffffu, part1, 2);
        if ((lane & 3) == 0) { s_log[m_lo] = part0; s_log[m_hi] = part1; }
        __syncthreads();
        // ---- softmax per pair (serial, 10 threads, deterministic) ----
        if (tid < PPT) {
            const float* lg = s_log + tid * KADJ;
            float mx = lg[0];
            #pragma unroll
            for (int k = 1; k < KADJ; k++) mx = fmaxf(mx, lg[k]);
            float e[KADJ], ssum = 0.f;
            #pragma unroll
            for (int k = 0; k < KADJ; k++) { e[k] = __expf(lg[k] - mx); ssum += e[k]; }
            const float inv = 1.f / ssum;
            #pragma unroll
            for (int k = 0; k < KADJ; k++) s_alp[tid * KADJ + k] = e[k] * inv;
        }
        __syncthreads();
        // ---- att = sum_k alpha * adj (fp32 exact) ----
        #pragma unroll
        for (int i = tid; i < PPT * D_; i += 256) {
            const int p = i >> 7, d = i & 127;
            const float* adp = s_adj + p * (KADJ * D_) + d;
            float a = 0.f;
            #pragma unroll
            for (int k = 0; k < KADJ; k++) a = fmaf(s_alp[p * KADJ + k], adp[k * D_], a);
            g_att[(pbase + p) * D_ + d] = a;
        }
    }
}

// -------------------------------------------------------- kernel2 (w3 + relu)
#define K2_B    0         // 131072 : w3 frags interleaved uint4 [ks16][nt16][lane]
#define K2_A    131072    // 32768  : A frags fp16 [ks8][mt8][lane][uint4]
#define K2_SIZE 163840

__global__ void __launch_bounds__(256, 1) kernel2(const float* __restrict__ itm,
                                                  float* __restrict__ out) {
    extern __shared__ __align__(16) unsigned char sm[];
    const int tid = threadIdx.x, warp = tid >> 5, lane = tid & 31;
    uint4* sB4 = (uint4*)(sm + K2_B);
    uint4* sA4 = (uint4*)(sm + K2_A);

    for (int i = tid; i < 16 * 16 * 32; i += 256) sB4[i] = g_w3B[i];

    const size_t rowbase = (size_t)blockIdx.x * 128;
    float acc[16][4];
    #pragma unroll
    for (int nt = 0; nt < 16; nt++)
        #pragma unroll
        for (int q = 0; q < 4; q++) acc[nt][q] = 0.f;

    #pragma unroll
    for (int half = 0; half < 2; half++) {
        const float* src = half ? (const float*)g_att : itm;
        __syncthreads();   // A buffer free (half 0: after B copy; half 1: after mma reads)
        for (int f = tid; f < 2048; f += 256) {
            const int ln = f & 31, mt = (f >> 5) & 7, ks = f >> 8;
            const size_t ra = rowbase + mt * 16 + (ln >> 2), rb = ra + 8;
            const int k0 = ks * 16 + (ln & 3) * 2, k8 = k0 + 8;
            float2 fa0 = *(const float2*)(src + ra * D_ + k0);
            float2 fb0 = *(const float2*)(src + rb * D_ + k0);
            float2 fa8 = *(const float2*)(src + ra * D_ + k8);
            float2 fb8 = *(const float2*)(src + rb * D_ + k8);
            uint4 H;
            H.x = h2(fa0.x, fa0.y);
            H.y = h2(fb0.x, fb0.y);
            H.z = h2(fa8.x, fa8.y);
            H.w = h2(fb8.x, fb8.y);
            sA4[f] = H;
        }
        __syncthreads();
        #pragma unroll
        for (int ks = 0; ks < 8; ks++) {
            const int gks = half * 8 + ks;
            const uint4 A = sA4[(ks * 8 + warp) * 32 + lane];
            #pragma unroll
            for (int nt = 0; nt < 16; nt++) {
                const uint4 B = sB4[(gks * 16 + nt) * 32 + lane];
                mma_fp16(acc[nt], A, B.x, B.y);
                mma_fp16(acc[nt], A, B.z, B.w);
            }
        }
    }
    // relu + unscale + store
    const size_t r_lo = rowbase + warp * 16 + (lane >> 2), r_hi = r_lo + 8;
    #pragma unroll
    for (int nt = 0; nt < 16; nt++) {
        const int c = nt * 8 + (lane & 3) * 2;
        *(float2*)(out + r_lo * D_ + c) =
            make_float2(fmaxf(acc[nt][0], 0.f) * IWSC, fmaxf(acc[nt][1], 0.f) * IWSC);
        *(float2*)(out + r_hi * D_ + c) =
            make_float2(fmaxf(acc[nt][2], 0.f) * IWSC, fmaxf(acc[nt][3], 0.f) * IWSC);
    }
}

// ------------------------------------------------------------------ launch
extern "C" void kernel_launch(void* const* d_in, const int* in_sizes, int n_in,
                              void* d_out, int out_size) {
    const float *itm = nullptr, *ave = nullptr, *adj = nullptr, *wgt = nullptr;
    const float *w1 = nullptr, *w2 = nullptr, *w3 = nullptr;
    for (int i = 0; i < n_in; i++) {
        const float* p = (const float*)d_in[i];
        switch (in_sizes[i]) {
            case 1638400:  if (!itm) itm = p; else ave = p; break;  // itm first, then ave
            case 19660800: adj = p; break;
            case 153600:   wgt = p; break;
            case 16512:    w1 = p; break;
            case 128:      w2 = p; break;
            case 32768:    w3 = p; break;
            default: break;
        }
    }
    cudaFuncSetAttribute(kernel1, cudaFuncAttributeMaxDynamicSharedMemorySize, K1_SIZE);
    cudaFuncSetAttribute(kernel2, cudaFuncAttributeMaxDynamicSharedMemorySize, K2_SIZE);

    prep_frags<<<48, 256>>>(w1, w3);
    kernel1<<<GRID1, 256, K1_SIZE>>>(ave, adj, wgt, w1, w2);
    kernel2<<<PAIRS / 128, 256, K2_SIZE>>>(itm, (float*)d_out);
}

// round 11
// speedup vs baseline: 2.3639x; 1.6310x over previous
#include <cuda_runtime.h>
#include <cuda_fp16.h>
#include <cstdint>
#include <cstddef>

// Shapes: B=256, N=50 -> PAIRS=12800; KADJ=12; D=128
#define PAIRS   12800
#define D_      128
#define KADJ    12
#define PPT     10            // pairs per tile (120 rows + 8 pad = 128)
#define TILES1  (PAIRS / PPT) // 1280
#define GRID1   148           // persistent CTAs
#define WSC     16.0f         // weight pre-scale (keeps fp16 residuals normal)
#define IWSC    0.0625f

// ------------------------------------------------------------------ scratch
// B fragments interleaved: uint4 = (Bh_r0, Bh_r1, Bl_r0, Bl_r1), index [ks][nt][lane]
__device__ __align__(16) uint4 g_w1B[8 * 16 * 32];     // w1 (K=128, N=128), 64KB
__device__ __align__(16) uint4 g_w3B[16 * 16 * 32];    // w3 (K=256, N=128), 128KB
__device__ float g_att[(size_t)PAIRS * D_];

// ------------------------------------------------------------------ helpers
__device__ __forceinline__ uint32_t h2(float v0, float v1) {
    __half2 h = __floats2half2_rn(v0, v1);
    uint32_t u; memcpy(&u, &h, 4); return u;
}
__device__ __forceinline__ void split16(float v, float& hi, float& lo) {
    hi = __half2float(__float2half_rn(v));
    lo = v - hi;
}
__device__ __forceinline__ void mma_fp16(float* c, uint4 a, uint32_t b0, uint32_t b1) {
    asm volatile(
        "mma.sync.aligned.m16n8k16.row.col.f32.f16.f16.f32 "
        "{%0,%1,%2,%3}, {%4,%5,%6,%7}, {%8,%9}, {%0,%1,%2,%3};\n"
        : "+f"(c[0]), "+f"(c[1]), "+f"(c[2]), "+f"(c[3])
        : "r"(a.x), "r"(a.y), "r"(a.z), "r"(a.w), "r"(b0), "r"(b1));
}
__device__ __forceinline__ uint32_t smem_u32(const void* p) {
    uint32_t a;
    asm("{ .reg .u64 t; cvta.to.shared.u64 t, %1; cvt.u32.u64 %0, t; }" : "=r"(a) : "l"(p));
    return a;
}
#define CP16(dst_u32, src_ptr) \
    asm volatile("cp.async.cg.shared.global [%0], [%1], 16;" :: "r"(dst_u32), "l"(src_ptr))
#define CP_COMMIT() asm volatile("cp.async.commit_group;" ::: "memory")
#define CP_WAIT0()  asm volatile("cp.async.wait_group 0;" ::: "memory")

// -------------------------------------------------------- prep: B fragments
// B-frag element map (m16n8k16): n = nt*8 + lane/4 ; reg r: k = ks*16 + (lane%4)*2 + r*8 + {0,1}
__global__ void prep_frags(const float* __restrict__ w1, const float* __restrict__ w3) {
    int idx = blockIdx.x * blockDim.x + threadIdx.x;
    if (idx < 8 * 16 * 32) {
        int lane = idx & 31, nt = (idx >> 5) & 15, ks = idx >> 9;
        int n  = nt * 8 + (lane >> 2);
        int k0 = ks * 16 + (lane & 3) * 2;
        float v00 = w1[k0 * 128 + n] * WSC,       v01 = w1[(k0 + 1) * 128 + n] * WSC;
        float v10 = w1[(k0 + 8) * 128 + n] * WSC, v11 = w1[(k0 + 9) * 128 + n] * WSC;
        float h00, l00, h01, l01, h10, l10, h11, l11;
        split16(v00, h00, l00); split16(v01, h01, l01);
        split16(v10, h10, l10); split16(v11, h11, l11);
        uint4 B;
        B.x = h2(h00, h01); B.y = h2(h10, h11);
        B.z = h2(l00, l01); B.w = h2(l10, l11);
        g_w1B[idx] = B;
    } else if (idx < 8 * 16 * 32 + 16 * 16 * 32) {
        int j = idx - 8 * 16 * 32;
        int lane = j & 31, nt = (j >> 5) & 15, ks = j >> 9;
        int n  = nt * 8 + (lane >> 2);
        int k0 = ks * 16 + (lane & 3) * 2;
        float v00 = w3[k0 * 128 + n] * WSC,       v01 = w3[(k0 + 1) * 128 + n] * WSC;
        float v10 = w3[(k0 + 8) * 128 + n] * WSC, v11 = w3[(k0 + 9) * 128 + n] * WSC;
        float h00, l00, h01, l01, h10, l10, h11, l11;
        split16(v00, h00, l00); split16(v01, h01, l01);
        split16(v10, h10, l10); split16(v11, h11, l11);
        uint4 B;
        B.x = h2(h00, h01); B.y = h2(h10, h11);
        B.z = h2(l00, l01); B.w = h2(l10, l11);
        g_w3B[j] = B;
    }
}

// -------------------------------------------------------- kernel1 (attention)
// smem byte offsets (double-buffered raw tiles)
// NOTE: K1_B holds 4096 uint2 = 32768 bytes (hi halves of 8*16*32 fragments)
#define K1_A     0        // 32768 : A frags fp16 [ks8][mt8][lane][uint4]
#define K1_B     32768    // 32768 : w1 B frags HI only, uint2 [ks8][nt16][lane]
#define K1_ADJ0  65536    // 61440
#define K1_ADJ1  126976   // 61440
#define K1_AVE0  188416   // 5120
#define K1_AVE1  193536   // 5120
#define K1_WGT0  198656   // 512
#define K1_WGT1  199168   // 512
#define K1_W1L   199680   // 512
#define K1_W2    200192   // 512
#define K1_LOG   200704   // 512
#define K1_ALP   201216   // 512
#define K1_SIZE  201728

__global__ void __launch_bounds__(256, 1) kernel1(
    const float* __restrict__ ave_g, const float* __restrict__ adj_g,
    const float* __restrict__ wgt_g, const float* __restrict__ w1_g,
    const float* __restrict__ w2_g) {
    extern __shared__ __align__(16) unsigned char sm[];
    const int tid = threadIdx.x, warp = tid >> 5, lane = tid & 31;
    const uint32_t sbase = smem_u32(sm);

    uint4* sA4 = (uint4*)(sm + K1_A);
    uint2* sB2 = (uint2*)(sm + K1_B);
    float* s_w1l = (float*)(sm + K1_W1L);
    float* s_w2  = (float*)(sm + K1_W2);
    float* s_log = (float*)(sm + K1_LOG);
    float* s_alp = (float*)(sm + K1_ALP);

    // ---- prefetch first tile (overlaps with B staging below) ----
    const int tile0 = blockIdx.x;
    {
        const char* adjp = (const char*)(adj_g + (size_t)tile0 * PPT * KADJ * D_);
        const char* avep = (const char*)(ave_g + (size_t)tile0 * PPT * D_);
        const char* wgtp = (const char*)(wgt_g + (size_t)tile0 * PPT * KADJ);
        for (int i = tid; i < 3840; i += 256) CP16(sbase + K1_ADJ0 + i * 16, adjp + i * 16);
        for (int i = tid; i < 320; i += 256)  CP16(sbase + K1_AVE0 + i * 16, avep + i * 16);
        if (tid < 30)                         CP16(sbase + K1_WGT0 + tid * 16, wgtp + tid * 16);
        CP_COMMIT();
    }
    // stage w1 B frags (hi halves only) + small vectors
    for (int i = tid; i < 4096; i += 256) {
        uint4 v = g_w1B[i];
        sB2[i] = make_uint2(v.x, v.y);
    }
    if (tid < 128) { s_w2[tid] = w2_g[tid]; s_w1l[tid] = w1_g[128 * 128 + tid]; }

    // per-lane constants (C-frag row map)
    const int m_lo = warp * 16 + (lane >> 2), m_hi = m_lo + 8;
    const int p_lo = m_lo / 12, kk_lo = m_lo - p_lo * 12;
    const int p_hi = m_hi / 12, kk_hi = m_hi - p_hi * 12;
    const bool v_lo = m_lo < PPT * KADJ, v_hi = m_hi < PPT * KADJ;

    int it = 0;
    for (int tile = tile0; tile < TILES1; tile += GRID1, it++) {
        const int cur = it & 1;
        float* s_adj = (float*)(sm + (cur ? K1_ADJ1 : K1_ADJ0));
        float* s_ave = (float*)(sm + (cur ? K1_AVE1 : K1_AVE0));
        float* s_wgt = (float*)(sm + (cur ? K1_WGT1 : K1_WGT0));

        CP_WAIT0();
        __syncthreads();   // current buffers landed everywhere; prev tile fully consumed

        // ---- build A = pre fragments (single fp16), frag f=[ks][mt][lane] ----
        for (int f = tid; f < 2048; f += 256) {
            const int ln = f & 31, mt = (f >> 5) & 7, ks = f >> 8;
            const int ma = mt * 16 + (ln >> 2), mb = ma + 8;
            const int k0 = ks * 16 + (ln & 3) * 2, k8 = k0 + 8;
            const int pa = ma / 12, ka = ma - pa * 12; const bool va = ma < 120;
            const int pb = mb / 12, kb = mb - pb * 12; const bool vb = mb < 120;
            float2 z = make_float2(0.f, 0.f);
            float2 aa0 = va ? *(const float2*)(s_ave + pa * D_ + k0) : z;
            float2 aa8 = va ? *(const float2*)(s_ave + pa * D_ + k8) : z;
            float2 ab0 = vb ? *(const float2*)(s_ave + pb * D_ + k0) : z;
            float2 ab8 = vb ? *(const float2*)(s_ave + pb * D_ + k8) : z;
            float2 da0 = va ? *(const float2*)(s_adj + (pa * KADJ + ka) * D_ + k0) : z;
            float2 da8 = va ? *(const float2*)(s_adj + (pa * KADJ + ka) * D_ + k8) : z;
            float2 db0 = vb ? *(const float2*)(s_adj + (pb * KADJ + kb) * D_ + k0) : z;
            float2 db8 = vb ? *(const float2*)(s_adj + (pb * KADJ + kb) * D_ + k8) : z;
            uint4 H;
            H.x = h2(aa0.x * da0.x, aa0.y * da0.y);
            H.y = h2(ab0.x * db0.x, ab0.y * db0.y);
            H.z = h2(aa8.x * da8.x, aa8.y * da8.y);
            H.w = h2(ab8.x * db8.x, ab8.y * db8.y);
            sA4[f] = H;
        }
        __syncthreads();   // A ready; other-buffer consumers (tile-1) long done

        // ---- prefetch next tile into the other buffer (hidden under mma) ----
        {
            const int nxt = tile + GRID1;
            if (nxt < TILES1) {
                const uint32_t oadj = cur ? K1_ADJ0 : K1_ADJ1;
                const uint32_t oave = cur ? K1_AVE0 : K1_AVE1;
                const uint32_t owgt = cur ? K1_WGT0 : K1_WGT1;
                const char* adjp = (const char*)(adj_g + (size_t)nxt * PPT * KADJ * D_);
                const char* avep = (const char*)(ave_g + (size_t)nxt * PPT * D_);
                const char* wgtp = (const char*)(wgt_g + (size_t)nxt * PPT * KADJ);
                for (int i = tid; i < 3840; i += 256) CP16(sbase + oadj + i * 16, adjp + i * 16);
                for (int i = tid; i < 320; i += 256)  CP16(sbase + oave + i * 16, avep + i * 16);
                if (tid < 30)                         CP16(sbase + owgt + tid * 16, wgtp + tid * 16);
            }
            CP_COMMIT();
        }

        // ---- GEMM1: 16 independent n-tiles per warp, hi-product only ----
        float acc[16][4];
        #pragma unroll
        for (int nt = 0; nt < 16; nt++)
            #pragma unroll
            for (int q = 0; q < 4; q++) acc[nt][q] = 0.f;
        #pragma unroll
        for (int ks = 0; ks < 8; ks++) {
            const uint4 A = sA4[(ks * 8 + warp) * 32 + lane];
            #pragma unroll
            for (int nt = 0; nt < 16; nt++) {
                const uint2 B = sB2[(ks * 16 + nt) * 32 + lane];
                mma_fp16(acc[nt], A, B.x, B.y);
            }
        }
        // ---- epilogue: unscale + rank-1 wgt correction + leaky + w2 dot ----
        const float wv_lo = v_lo ? s_wgt[p_lo * KADJ + kk_lo] : 0.f;
        const float wv_hi = v_hi ? s_wgt[p_hi * KADJ + kk_hi] : 0.f;
        float part0 = 0.f, part1 = 0.f;
        #pragma unroll
        for (int nt = 0; nt < 16; nt++) {
            #pragma unroll
            for (int j = 0; j < 2; j++) {
                const int c = nt * 8 + (lane & 3) * 2 + j;
                const float w1lc = s_w1l[c], w2c = s_w2[c];
                float a = fmaf(wv_lo, w1lc, acc[nt][j] * IWSC);
                part0 = fmaf(fmaxf(a, 0.2f * a), w2c, part0);
                float b = fmaf(wv_hi, w1lc, acc[nt][2 + j] * IWSC);
                part1 = fmaf(fmaxf(b, 0.2f * b), w2c, part1);
            }
        }
        part0 += __shfl_xor_sync(0xffffffffu, part0, 1);
        part0 += __shfl_xor_sync(0xffffffffu, part0, 2);
        part1 += __shfl_xor_sync(0xffffffffu, part1, 1);
        part1 += __shfl_xor_sync(0xffffffffu, part1, 2);
        if ((lane & 3) == 0) { s_log[m_lo] = part0; s_log[m_hi] = part1; }
        __syncthreads();
        // ---- softmax per pair (serial, 10 threads, deterministic) ----
        if (tid < PPT) {
            const float* lg = s_log + tid * KADJ;
            float mx = lg[0];
            #pragma unroll
            for (int k = 1; k < KADJ; k++) mx = fmaxf(mx, lg[k]);
            float e[KADJ], ssum = 0.f;
            #pragma unroll
            for (int k = 0; k < KADJ; k++) { e[k] = __expf(lg[k] - mx); ssum += e[k]; }
            const float inv = 1.f / ssum;
            #pragma unroll
            for (int k = 0; k < KADJ; k++) s_alp[tid * KADJ + k] = e[k] * inv;
        }
        __syncthreads();
        // ---- att = sum_k alpha * adj (fp32 exact) ----
        const size_t pbase = (size_t)tile * PPT;
        #pragma unroll
        for (int i = tid; i < PPT * D_; i += 256) {
            const int p = i >> 7, d = i & 127;
            const float* adp = s_adj + p * (KADJ * D_) + d;
            float a = 0.f;
            #pragma unroll
            for (int k = 0; k < KADJ; k++) a = fmaf(s_alp[p * KADJ + k], adp[k * D_], a);
            g_att[(pbase + p) * D_ + d] = a;
        }
    }
}

// -------------------------------------------------------- kernel2 (w3 + relu)
#define K2_B    0         // 131072 : w3 frags interleaved uint4 [ks16][nt16][lane]
#define K2_A    131072    // 32768  : A frags fp16 [ks8][mt8][lane][uint4]
#define K2_SIZE 163840

__global__ void __launch_bounds__(256, 1) kernel2(const float* __restrict__ itm,
                                                  float* __restrict__ out) {
    extern __shared__ __align__(16) unsigned char sm[];
    const int tid = threadIdx.x, warp = tid >> 5, lane = tid & 31;
    uint4* sB4 = (uint4*)(sm + K2_B);
    uint4* sA4 = (uint4*)(sm + K2_A);

    for (int i = tid; i < 16 * 16 * 32; i += 256) sB4[i] = g_w3B[i];

    const size_t rowbase = (size_t)blockIdx.x * 128;
    float acc[16][4];
    #pragma unroll
    for (int nt = 0; nt < 16; nt++)
        #pragma unroll
        for (int q = 0; q < 4; q++) acc[nt][q] = 0.f;

    #pragma unroll
    for (int half = 0; half < 2; half++) {
        const float* src = half ? (const float*)g_att : itm;
        __syncthreads();   // A buffer free (half 0: after B copy; half 1: after mma reads)
        for (int f = tid; f < 2048; f += 256) {
            const int ln = f & 31, mt = (f >> 5) & 7, ks = f >> 8;
            const size_t ra = rowbase + mt * 16 + (ln >> 2), rb = ra + 8;
            const int k0 = ks * 16 + (ln & 3) * 2, k8 = k0 + 8;
            float2 fa0 = *(const float2*)(src + ra * D_ + k0);
            float2 fb0 = *(const float2*)(src + rb * D_ + k0);
            float2 fa8 = *(const float2*)(src + ra * D_ + k8);
            float2 fb8 = *(const float2*)(src + rb * D_ + k8);
            uint4 H;
            H.x = h2(fa0.x, fa0.y);
            H.y = h2(fb0.x, fb0.y);
            H.z = h2(fa8.x, fa8.y);
            H.w = h2(fb8.x, fb8.y);
            sA4[f] = H;
        }
        __syncthreads();
        #pragma unroll
        for (int ks = 0; ks < 8; ks++) {
            const int gks = half * 8 + ks;
            const uint4 A = sA4[(ks * 8 + warp) * 32 + lane];
            #pragma unroll
            for (int nt = 0; nt < 16; nt++) {
                const uint4 B = sB4[(gks * 16 + nt) * 32 + lane];
                mma_fp16(acc[nt], A, B.x, B.y);
                mma_fp16(acc[nt], A, B.z, B.w);
            }
        }
    }
    // relu + unscale + store
    const size_t r_lo = rowbase + warp * 16 + (lane >> 2), r_hi = r_lo + 8;
    #pragma unroll
    for (int nt = 0; nt < 16; nt++) {
        const int c = nt * 8 + (lane & 3) * 2;
        *(float2*)(out + r_lo * D_ + c) =
            make_float2(fmaxf(acc[nt][0], 0.f) * IWSC, fmaxf(acc[nt][1], 0.f) * IWSC);
        *(float2*)(out + r_hi * D_ + c) =
            make_float2(fmaxf(acc[nt][2], 0.f) * IWSC, fmaxf(acc[nt][3], 0.f) * IWSC);
    }
}

// ------------------------------------------------------------------ launch
extern "C" void kernel_launch(void* const* d_in, const int* in_sizes, int n_in,
                              void* d_out, int out_size) {
    const float *itm = nullptr, *ave = nullptr, *adj = nullptr, *wgt = nullptr;
    const float *w1 = nullptr, *w2 = nullptr, *w3 = nullptr;
    for (int i = 0; i < n_in; i++) {
        const float* p = (const float*)d_in[i];
        switch (in_sizes[i]) {
            case 1638400:  if (!itm) itm = p; else ave = p; break;  // itm first, then ave
            case 19660800: adj = p; break;
            case 153600:   wgt = p; break;
            case 16512:    w1 = p; break;
            case 128:      w2 = p; break;
            case 32768:    w3 = p; break;
            default: break;
        }
    }
    cudaFuncSetAttribute(kernel1, cudaFuncAttributeMaxDynamicSharedMemorySize, K1_SIZE);
    cudaFuncSetAttribute(kernel2, cudaFuncAttributeMaxDynamicSharedMemorySize, K2_SIZE);

    prep_frags<<<48, 256>>>(w1, w3);
    kernel1<<<GRID1, 256, K1_SIZE>>>(ave, adj, wgt, w1, w2);
    kernel2<<<PAIRS / 128, 256, K2_SIZE>>>(itm, (float*)d_out);
}